// round 1
// baseline (speedup 1.0000x reference)
#include <cuda_runtime.h>

#define RR 128
#define BASIS 9
#define DATA_DIM 28
#define NUM_STEPS 256
#define STEP_SIZE 0.001f
#define BG 1.0f

__global__ void __launch_bounds__(256)
volrend_kernel(const float* __restrict__ tree,      // [R,R,R,28]
               const float* __restrict__ origins,   // [B,3]
               const float* __restrict__ dirs,      // [B,3]
               const float* __restrict__ viewdirs,  // [B,3]
               const float* __restrict__ invradius, // [3]
               float* __restrict__ out,             // [B,3]
               int nb)
{
    int i = blockIdx.x * blockDim.x + threadIdx.x;
    if (i >= nb) return;

    float ox = origins[3*i+0], oy = origins[3*i+1], oz = origins[3*i+2];
    float dx = dirs[3*i+0],    dy = dirs[3*i+1],    dz = dirs[3*i+2];
    float inv_norm = rsqrtf(dx*dx + dy*dy + dz*dz);
    dx *= inv_norm; dy *= inv_norm; dz *= inv_norm;

    float vx = viewdirs[3*i+0], vy = viewdirs[3*i+1], vz = viewdirs[3*i+2];

    // SH bases (2nd order, 9 coeffs)
    float sh[BASIS];
    sh[0] =  0.28209479177387814f;
    sh[1] = -0.4886025119029199f * vy;
    sh[2] =  0.4886025119029199f * vz;
    sh[3] = -0.4886025119029199f * vx;
    sh[4] =  1.0925484305920792f * vx * vy;
    sh[5] = -1.0925484305920792f * vy * vz;
    sh[6] =  0.31539156525252005f * (2.0f*vz*vz - vx*vx - vy*vy);
    sh[7] = -1.0925484305920792f * vx * vz;
    sh[8] =  0.5462742152960396f * (vx*vx - vy*vy);

    float idrx = 1.0f / (dx + 1e-9f);
    float idry = 1.0f / (dy + 1e-9f);
    float idrz = 1.0f / (dz + 1e-9f);

    // dda_unit(origins, invdirs)
    float t1x = -ox * idrx, t2x = t1x + idrx;
    float t1y = -oy * idry, t2y = t1y + idry;
    float t1z = -oz * idrz, t2z = t1z + idrz;
    float tmin = fmaxf(fmaxf(fminf(t1x,t2x), fminf(t1y,t2y)), fminf(t1z,t2z));
    tmin = fmaxf(tmin, 0.0f);
    float tmax = fminf(fminf(fmaxf(t1x,t2x), fmaxf(t1y,t2y)), fmaxf(t1z,t2z));
    tmax = fminf(tmax, 1e9f);

    float irx = invradius[0], iry = invradius[1], irz = invradius[2];
    float dsx = dx / irx, dsy = dy / iry, dsz = dz / irz;
    float delta_scale = sqrtf(dsx*dsx + dsy*dsy + dsz*dsz);

    float t = tmin;
    float light = 1.0f;
    float out0 = 0.0f, out1 = 0.0f, out2 = 0.0f;
    const float cube_sz = 1.0f / (float)RR;

    if (tmin < tmax) {
        #pragma unroll 1
        for (int s = 0; s < NUM_STEPS; ++s) {
            float px = fmaf(t, dx, ox) * (float)RR;
            float py = fmaf(t, dy, oy) * (float)RR;
            float pz = fmaf(t, dz, oz) * (float)RR;
            float fx = fminf(fmaxf(floorf(px), 0.0f), (float)(RR-1));
            float fy = fminf(fmaxf(floorf(py), 0.0f), (float)(RR-1));
            float fz = fminf(fmaxf(floorf(pz), 0.0f), (float)(RR-1));
            int flat = (int)fx * (RR*RR) + (int)fy * RR + (int)fz;

            const float4* vp = reinterpret_cast<const float4*>(tree + (size_t)flat * DATA_DIM);
            float4 a0 = __ldg(vp + 0);
            float4 a1 = __ldg(vp + 1);
            float4 a2 = __ldg(vp + 2);
            float4 a3 = __ldg(vp + 3);
            float4 a4 = __ldg(vp + 4);
            float4 a5 = __ldg(vp + 5);
            float4 a6 = __ldg(vp + 6);

            // dda within unit cell
            float cx = px - fx, cy = py - fy, cz = pz - fz;
            float u1x = -cx * idrx, u2x = u1x + idrx;
            float u1y = -cy * idry, u2y = u1y + idry;
            float u1z = -cz * idrz, u2z = u1z + idrz;
            float s0 = fmaxf(fmaxf(fminf(u1x,u2x), fminf(u1y,u2y)), fminf(u1z,u2z));
            s0 = fmaxf(s0, 0.0f);
            float s1 = fminf(fminf(fmaxf(u1x,u2x), fmaxf(u1y,u2y)), fmaxf(u1z,u2z));
            s1 = fminf(s1, 1e9f);
            float dt = (s1 - s0) * cube_sz + STEP_SIZE;

            float sigma = fmaxf(a6.w, 0.0f);
            float att = expf(-dt * sigma * delta_scale);
            float weight = light * (1.0f - att);

            float rg[27] = {a0.x,a0.y,a0.z,a0.w, a1.x,a1.y,a1.z,a1.w,
                            a2.x,a2.y,a2.z,a2.w, a3.x,a3.y,a3.z,a3.w,
                            a4.x,a4.y,a4.z,a4.w, a5.x,a5.y,a5.z,a5.w,
                            a6.x,a6.y,a6.z};

            float c0 = 0.0f, c1 = 0.0f, c2 = 0.0f;
            #pragma unroll
            for (int j = 0; j < BASIS; ++j) {
                c0 = fmaf(sh[j], rg[j],          c0);
                c1 = fmaf(sh[j], rg[BASIS + j],  c1);
                c2 = fmaf(sh[j], rg[2*BASIS + j], c2);
            }
            float r0 = 1.0f / (1.0f + expf(-c0));
            float r1 = 1.0f / (1.0f + expf(-c1));
            float r2 = 1.0f / (1.0f + expf(-c2));

            out0 = fmaf(weight, r0, out0);
            out1 = fmaf(weight, r1, out1);
            out2 = fmaf(weight, r2, out2);
            light *= att;
            t += dt;
            if (t >= tmax) break;
        }
    }

    out[3*i+0] = out0 + light * BG;
    out[3*i+1] = out1 + light * BG;
    out[3*i+2] = out2 + light * BG;
}

extern "C" void kernel_launch(void* const* d_in, const int* in_sizes, int n_in,
                              void* d_out, int out_size)
{
    const float* tree      = (const float*)d_in[0];
    const float* origins   = (const float*)d_in[1];
    const float* dirs      = (const float*)d_in[2];
    const float* viewdirs  = (const float*)d_in[3];
    const float* invradius = (const float*)d_in[4];
    float* out = (float*)d_out;

    int nb = in_sizes[1] / 3;  // origins is [B,3]
    int threads = 256;
    int blocks = (nb + threads - 1) / threads;
    volrend_kernel<<<blocks, threads>>>(tree, origins, dirs, viewdirs, invradius, out, nb);
}

// round 2
// speedup vs baseline: 1.5349x; 1.5349x over previous
#include <cuda_runtime.h>

#define RR 128
#define BASIS 9
#define DATA_DIM 28
#define NUM_STEPS 256
#define STEP_SIZE 0.001f
#define BG 1.0f

__global__ void __launch_bounds__(128)
volrend_kernel(const float* __restrict__ tree,      // [R,R,R,28]
               const float* __restrict__ origins,   // [B,3]
               const float* __restrict__ dirs,      // [B,3]
               const float* __restrict__ viewdirs,  // [B,3]
               const float* __restrict__ invradius, // [3]
               float* __restrict__ out,             // [B,3]
               int nb)
{
    int i = blockIdx.x * blockDim.x + threadIdx.x;
    if (i >= nb) return;

    float ox = origins[3*i+0], oy = origins[3*i+1], oz = origins[3*i+2];
    float dx = dirs[3*i+0],    dy = dirs[3*i+1],    dz = dirs[3*i+2];
    float inv_norm = rsqrtf(dx*dx + dy*dy + dz*dz);
    dx *= inv_norm; dy *= inv_norm; dz *= inv_norm;

    float vx = viewdirs[3*i+0], vy = viewdirs[3*i+1], vz = viewdirs[3*i+2];

    // SH bases (2nd order, 9 coeffs)
    float sh[BASIS];
    sh[0] =  0.28209479177387814f;
    sh[1] = -0.4886025119029199f * vy;
    sh[2] =  0.4886025119029199f * vz;
    sh[3] = -0.4886025119029199f * vx;
    sh[4] =  1.0925484305920792f * vx * vy;
    sh[5] = -1.0925484305920792f * vy * vz;
    sh[6] =  0.31539156525252005f * (2.0f*vz*vz - vx*vx - vy*vy);
    sh[7] = -1.0925484305920792f * vx * vz;
    sh[8] =  0.5462742152960396f * (vx*vx - vy*vy);

    float idrx = 1.0f / (dx + 1e-9f);
    float idry = 1.0f / (dy + 1e-9f);
    float idrz = 1.0f / (dz + 1e-9f);

    // dda_unit(origins, invdirs)
    float t1x = -ox * idrx, t2x = t1x + idrx;
    float t1y = -oy * idry, t2y = t1y + idry;
    float t1z = -oz * idrz, t2z = t1z + idrz;
    float tmin = fmaxf(fmaxf(fminf(t1x,t2x), fminf(t1y,t2y)), fminf(t1z,t2z));
    tmin = fmaxf(tmin, 0.0f);
    float tmax = fminf(fminf(fmaxf(t1x,t2x), fmaxf(t1y,t2y)), fmaxf(t1z,t2z));
    tmax = fminf(tmax, 1e9f);

    float irx = invradius[0], iry = invradius[1], irz = invradius[2];
    float dsx = dx / irx, dsy = dy / iry, dsz = dz / irz;
    float delta_scale = sqrtf(dsx*dsx + dsy*dsy + dsz*dsz);

    float t = tmin;
    float light = 1.0f;
    float out0 = 0.0f, out1 = 0.0f, out2 = 0.0f;
    const float cube_sz = 1.0f / (float)RR;

    // Geometry at parameter tt: dt and voxel base pointer. Pure ALU — no
    // dependence on loaded voxel data, so it can run ahead of the gathers.
    #define GEOM(tt, dt_o, vp_o)                                               \
    {                                                                          \
        float px = fmaf((tt), dx, ox) * (float)RR;                             \
        float py = fmaf((tt), dy, oy) * (float)RR;                             \
        float pz = fmaf((tt), dz, oz) * (float)RR;                             \
        float fx = fminf(fmaxf(floorf(px), 0.0f), (float)(RR-1));              \
        float fy = fminf(fmaxf(floorf(py), 0.0f), (float)(RR-1));              \
        float fz = fminf(fmaxf(floorf(pz), 0.0f), (float)(RR-1));              \
        int flat = (int)fx * (RR*RR) + (int)fy * RR + (int)fz;                 \
        (vp_o) = reinterpret_cast<const float4*>(tree + (size_t)flat * DATA_DIM); \
        float cx = px - fx, cy = py - fy, cz = pz - fz;                        \
        float u1x = -cx * idrx, u2x = u1x + idrx;                              \
        float u1y = -cy * idry, u2y = u1y + idry;                              \
        float u1z = -cz * idrz, u2z = u1z + idrz;                              \
        float s0 = fmaxf(fmaxf(fminf(u1x,u2x), fminf(u1y,u2y)), fminf(u1z,u2z)); \
        s0 = fmaxf(s0, 0.0f);                                                  \
        float s1 = fminf(fminf(fmaxf(u1x,u2x), fmaxf(u1y,u2y)), fmaxf(u1z,u2z)); \
        s1 = fminf(s1, 1e9f);                                                  \
        (dt_o) = (s1 - s0) * cube_sz + STEP_SIZE;                              \
    }

    if (tmin < tmax) {
        // Prologue: geometry + loads for step 0
        float dt_cur;
        const float4* vp;
        GEOM(t, dt_cur, vp);
        float4 b0 = __ldg(vp + 0);
        float4 b1 = __ldg(vp + 1);
        float4 b2 = __ldg(vp + 2);
        float4 b3 = __ldg(vp + 3);
        float4 b4 = __ldg(vp + 4);
        float4 b5 = __ldg(vp + 5);
        float4 b6 = __ldg(vp + 6);

        #pragma unroll 1
        for (int s = 0; s < NUM_STEPS; ++s) {
            // Consume prefetched data
            float4 a0 = b0, a1 = b1, a2 = b2, a3 = b3, a4 = b4, a5 = b5, a6 = b6;
            float dt = dt_cur;

            // March ahead: next step geometry + issue next gather BEFORE shading
            float t_new = t + dt;
            bool more = (t_new < tmax) && (s + 1 < NUM_STEPS);
            float dt_next = 0.0f;
            if (more) {
                const float4* vpn;
                GEOM(t_new, dt_next, vpn);
                b0 = __ldg(vpn + 0);
                b1 = __ldg(vpn + 1);
                b2 = __ldg(vpn + 2);
                b3 = __ldg(vpn + 3);
                b4 = __ldg(vpn + 4);
                b5 = __ldg(vpn + 5);
                b6 = __ldg(vpn + 6);
            }

            // Shade current step (overlaps with in-flight next gather)
            float sigma = fmaxf(a6.w, 0.0f);
            float att = __expf(-dt * sigma * delta_scale);
            float weight = light * (1.0f - att);

            float rg[27] = {a0.x,a0.y,a0.z,a0.w, a1.x,a1.y,a1.z,a1.w,
                            a2.x,a2.y,a2.z,a2.w, a3.x,a3.y,a3.z,a3.w,
                            a4.x,a4.y,a4.z,a4.w, a5.x,a5.y,a5.z,a5.w,
                            a6.x,a6.y,a6.z};

            float c0 = 0.0f, c1 = 0.0f, c2 = 0.0f;
            #pragma unroll
            for (int j = 0; j < BASIS; ++j) {
                c0 = fmaf(sh[j], rg[j],            c0);
                c1 = fmaf(sh[j], rg[BASIS + j],    c1);
                c2 = fmaf(sh[j], rg[2*BASIS + j],  c2);
            }
            float r0 = __fdividef(1.0f, 1.0f + __expf(-c0));
            float r1 = __fdividef(1.0f, 1.0f + __expf(-c1));
            float r2 = __fdividef(1.0f, 1.0f + __expf(-c2));

            out0 = fmaf(weight, r0, out0);
            out1 = fmaf(weight, r1, out1);
            out2 = fmaf(weight, r2, out2);
            light *= att;

            t = t_new;
            dt_cur = dt_next;
            if (!more) break;
        }
    }
    #undef GEOM

    out[3*i+0] = out0 + light * BG;
    out[3*i+1] = out1 + light * BG;
    out[3*i+2] = out2 + light * BG;
}

extern "C" void kernel_launch(void* const* d_in, const int* in_sizes, int n_in,
                              void* d_out, int out_size)
{
    const float* tree      = (const float*)d_in[0];
    const float* origins   = (const float*)d_in[1];
    const float* dirs      = (const float*)d_in[2];
    const float* viewdirs  = (const float*)d_in[3];
    const float* invradius = (const float*)d_in[4];
    float* out = (float*)d_out;

    int nb = in_sizes[1] / 3;  // origins is [B,3]
    int threads = 128;
    int blocks = (nb + threads - 1) / threads;
    volrend_kernel<<<blocks, threads>>>(tree, origins, dirs, viewdirs, invradius, out, nb);
}

// round 3
// speedup vs baseline: 1.6779x; 1.0932x over previous
#include <cuda_runtime.h>
#include <cuda_fp16.h>

#define RR 128
#define BASIS 9
#define DATA_DIM 28
#define NUM_STEPS 256
#define STEP_SIZE 0.001f
#define BG 1.0f

#define NVOX (RR*RR*RR)           // 2097152
#define PAD_HALVES 32             // 28 used + 4 pad -> 64B per voxel

// Static scratch: fp16 packed grid, 64B/voxel, 16B-aligned via uint4.
// NVOX * 4 uint4 = 134,217,728 bytes.
__device__ uint4 g_grid[NVOX * 4];

// ---------------------------------------------------------------------------
// Conversion: fp32 [NVOX,28] -> fp16 [NVOX,32] (padded). One thread per half2.
// ---------------------------------------------------------------------------
__global__ void __launch_bounds__(256)
convert_kernel(const float* __restrict__ tree)
{
    int idx = blockIdx.x * blockDim.x + threadIdx.x;   // half2 index
    if (idx >= NVOX * (PAD_HALVES / 2)) return;
    int voxel = idx >> 4;           // 16 half2 per voxel
    int j2 = (idx & 15) * 2;        // first half index within voxel
    const float* src = tree + (size_t)voxel * DATA_DIM;
    float f0 = (j2     < DATA_DIM) ? src[j2]     : 0.0f;
    float f1 = (j2 + 1 < DATA_DIM) ? src[j2 + 1] : 0.0f;
    reinterpret_cast<__half2*>(g_grid)[idx] = __floats2half2_rn(f0, f1);
}

// ---------------------------------------------------------------------------
// Main renderer
// ---------------------------------------------------------------------------
__global__ void __launch_bounds__(128)
volrend_kernel(const float* __restrict__ origins,   // [B,3]
               const float* __restrict__ dirs,      // [B,3]
               const float* __restrict__ viewdirs,  // [B,3]
               const float* __restrict__ invradius, // [3]
               float* __restrict__ out,             // [B,3]
               int nb)
{
    int i = blockIdx.x * blockDim.x + threadIdx.x;
    if (i >= nb) return;

    float ox = origins[3*i+0], oy = origins[3*i+1], oz = origins[3*i+2];
    float dx = dirs[3*i+0],    dy = dirs[3*i+1],    dz = dirs[3*i+2];
    float inv_norm = rsqrtf(dx*dx + dy*dy + dz*dz);
    dx *= inv_norm; dy *= inv_norm; dz *= inv_norm;

    float vx = viewdirs[3*i+0], vy = viewdirs[3*i+1], vz = viewdirs[3*i+2];

    float sh[BASIS];
    sh[0] =  0.28209479177387814f;
    sh[1] = -0.4886025119029199f * vy;
    sh[2] =  0.4886025119029199f * vz;
    sh[3] = -0.4886025119029199f * vx;
    sh[4] =  1.0925484305920792f * vx * vy;
    sh[5] = -1.0925484305920792f * vy * vz;
    sh[6] =  0.31539156525252005f * (2.0f*vz*vz - vx*vx - vy*vy);
    sh[7] = -1.0925484305920792f * vx * vz;
    sh[8] =  0.5462742152960396f * (vx*vx - vy*vy);

    float idrx = 1.0f / (dx + 1e-9f);
    float idry = 1.0f / (dy + 1e-9f);
    float idrz = 1.0f / (dz + 1e-9f);

    float t1x = -ox * idrx, t2x = t1x + idrx;
    float t1y = -oy * idry, t2y = t1y + idry;
    float t1z = -oz * idrz, t2z = t1z + idrz;
    float tmin = fmaxf(fmaxf(fminf(t1x,t2x), fminf(t1y,t2y)), fminf(t1z,t2z));
    tmin = fmaxf(tmin, 0.0f);
    float tmax = fminf(fminf(fmaxf(t1x,t2x), fmaxf(t1y,t2y)), fmaxf(t1z,t2z));
    tmax = fminf(tmax, 1e9f);

    float irx = invradius[0], iry = invradius[1], irz = invradius[2];
    float dsx = dx / irx, dsy = dy / iry, dsz = dz / irz;
    float delta_scale = sqrtf(dsx*dsx + dsy*dsy + dsz*dsz);

    float t = tmin;
    float light = 1.0f;
    float out0 = 0.0f, out1 = 0.0f, out2 = 0.0f;
    const float cube_sz = 1.0f / (float)RR;

    // Geometry at parameter tt -> dt and voxel pointer. Pure ALU, independent
    // of loaded voxel data, so it runs ahead of the gather.
    #define GEOM(tt, dt_o, vp_o)                                               \
    {                                                                          \
        float px = fmaf((tt), dx, ox) * (float)RR;                             \
        float py = fmaf((tt), dy, oy) * (float)RR;                             \
        float pz = fmaf((tt), dz, oz) * (float)RR;                             \
        float fx = fminf(fmaxf(floorf(px), 0.0f), (float)(RR-1));              \
        float fy = fminf(fmaxf(floorf(py), 0.0f), (float)(RR-1));              \
        float fz = fminf(fmaxf(floorf(pz), 0.0f), (float)(RR-1));              \
        int flat = (int)fx * (RR*RR) + (int)fy * RR + (int)fz;                 \
        (vp_o) = g_grid + (size_t)flat * 4;                                    \
        float cx = px - fx, cy = py - fy, cz = pz - fz;                        \
        float u1x = -cx * idrx, u2x = u1x + idrx;                              \
        float u1y = -cy * idry, u2y = u1y + idry;                              \
        float u1z = -cz * idrz, u2z = u1z + idrz;                              \
        float s0 = fmaxf(fmaxf(fminf(u1x,u2x), fminf(u1y,u2y)), fminf(u1z,u2z)); \
        s0 = fmaxf(s0, 0.0f);                                                  \
        float s1 = fminf(fminf(fmaxf(u1x,u2x), fmaxf(u1y,u2y)), fmaxf(u1z,u2z)); \
        s1 = fminf(s1, 1e9f);                                                  \
        (dt_o) = (s1 - s0) * cube_sz + STEP_SIZE;                              \
    }

    if (tmin < tmax) {
        float dt_cur;
        const uint4* vp;
        GEOM(t, dt_cur, vp);
        uint4 b0 = __ldg(vp + 0);
        uint4 b1 = __ldg(vp + 1);
        uint4 b2 = __ldg(vp + 2);
        uint4 b3 = __ldg(vp + 3);

        #pragma unroll 1
        for (int s = 0; s < NUM_STEPS; ++s) {
            uint4 a0 = b0, a1 = b1, a2 = b2, a3 = b3;
            float dt = dt_cur;

            // Issue next step's gather before shading the current one.
            float t_new = t + dt;
            bool more = (t_new < tmax) && (s + 1 < NUM_STEPS);
            float dt_next = 0.0f;
            if (more) {
                const uint4* vpn;
                GEOM(t_new, dt_next, vpn);
                b0 = __ldg(vpn + 0);
                b1 = __ldg(vpn + 1);
                b2 = __ldg(vpn + 2);
                b3 = __ldg(vpn + 3);
            }

            // Unpack 32 halves (27 SH coeffs + sigma at [27])
            __half hs[PAD_HALVES];
            *reinterpret_cast<uint4*>(hs +  0) = a0;
            *reinterpret_cast<uint4*>(hs +  8) = a1;
            *reinterpret_cast<uint4*>(hs + 16) = a2;
            *reinterpret_cast<uint4*>(hs + 24) = a3;

            float sigma = fmaxf(__half2float(hs[27]), 0.0f);
            float att = __expf(-dt * sigma * delta_scale);
            float weight = light * (1.0f - att);

            float c0 = 0.0f, c1 = 0.0f, c2 = 0.0f;
            #pragma unroll
            for (int j = 0; j < BASIS; ++j) {
                c0 = fmaf(sh[j], __half2float(hs[j]),            c0);
                c1 = fmaf(sh[j], __half2float(hs[BASIS + j]),    c1);
                c2 = fmaf(sh[j], __half2float(hs[2*BASIS + j]),  c2);
            }
            float r0 = __fdividef(1.0f, 1.0f + __expf(-c0));
            float r1 = __fdividef(1.0f, 1.0f + __expf(-c1));
            float r2 = __fdividef(1.0f, 1.0f + __expf(-c2));

            out0 = fmaf(weight, r0, out0);
            out1 = fmaf(weight, r1, out1);
            out2 = fmaf(weight, r2, out2);
            light *= att;

            t = t_new;
            dt_cur = dt_next;
            if (!more) break;
        }
    }
    #undef GEOM

    out[3*i+0] = out0 + light * BG;
    out[3*i+1] = out1 + light * BG;
    out[3*i+2] = out2 + light * BG;
}

extern "C" void kernel_launch(void* const* d_in, const int* in_sizes, int n_in,
                              void* d_out, int out_size)
{
    const float* tree      = (const float*)d_in[0];
    const float* origins   = (const float*)d_in[1];
    const float* dirs      = (const float*)d_in[2];
    const float* viewdirs  = (const float*)d_in[3];
    const float* invradius = (const float*)d_in[4];
    float* out = (float*)d_out;

    int nb = in_sizes[1] / 3;

    // Pass 1: repack grid to fp16/64B
    int n_pairs = NVOX * (PAD_HALVES / 2);
    convert_kernel<<<(n_pairs + 255) / 256, 256>>>(tree);

    // Pass 2: render
    int threads = 128;
    int blocks = (nb + threads - 1) / threads;
    volrend_kernel<<<blocks, threads>>>(origins, dirs, viewdirs, invradius, out, nb);
}

// round 4
// speedup vs baseline: 1.9052x; 1.1355x over previous
#include <cuda_runtime.h>
#include <cuda_fp16.h>

#define RR 128
#define BASIS 9
#define DATA_DIM 28
#define NUM_STEPS 256
#define STEP_SIZE 0.001f
#define BG 1.0f

#define NVOX (RR*RR*RR)           // 2097152
#define PAD_HALVES 32             // 28 used + 4 pad -> 64B per voxel

// Static scratch: fp16 packed grid, 64B/voxel. NVOX * 4 uint4 = 128 MiB.
__device__ uint4 g_grid[NVOX * 4];

// ---------------------------------------------------------------------------
// Conversion: fp32 [NVOX,28] -> fp16 [NVOX,32]. One thread per uint4 output
// (8 halves): reads two aligned float4s, writes one uint4.
// ---------------------------------------------------------------------------
__global__ void __launch_bounds__(256)
convert_kernel(const float* __restrict__ tree)
{
    int idx = blockIdx.x * blockDim.x + threadIdx.x;   // uint4 index
    if (idx >= NVOX * 4) return;
    int voxel = idx >> 2;
    int q = idx & 3;
    // voxel record = 28 floats = 7 float4 (16B-aligned since 112 % 16 == 0)
    const float4* src = reinterpret_cast<const float4*>(tree) + (size_t)voxel * 7;
    float4 fa, fb;
    if (q < 3) {
        fa = __ldg(src + q * 2);
        fb = __ldg(src + q * 2 + 1);
    } else {
        fa = __ldg(src + 6);                 // floats 24..27
        fb = make_float4(0.f, 0.f, 0.f, 0.f); // pad 28..31
    }
    __half2 h0 = __floats2half2_rn(fa.x, fa.y);
    __half2 h1 = __floats2half2_rn(fa.z, fa.w);
    __half2 h2 = __floats2half2_rn(fb.x, fb.y);
    __half2 h3 = __floats2half2_rn(fb.z, fb.w);
    uint4 o;
    o.x = *reinterpret_cast<unsigned*>(&h0);
    o.y = *reinterpret_cast<unsigned*>(&h1);
    o.z = *reinterpret_cast<unsigned*>(&h2);
    o.w = *reinterpret_cast<unsigned*>(&h3);
    g_grid[idx] = o;
}

// ---------------------------------------------------------------------------
// Main renderer with depth-2 software pipeline (addresses are data-independent)
// ---------------------------------------------------------------------------
__global__ void __launch_bounds__(128)
volrend_kernel(const float* __restrict__ origins,   // [B,3]
               const float* __restrict__ dirs,      // [B,3]
               const float* __restrict__ viewdirs,  // [B,3]
               const float* __restrict__ invradius, // [3]
               float* __restrict__ out,             // [B,3]
               int nb)
{
    int i = blockIdx.x * blockDim.x + threadIdx.x;
    if (i >= nb) return;

    float ox = origins[3*i+0], oy = origins[3*i+1], oz = origins[3*i+2];
    float dx = dirs[3*i+0],    dy = dirs[3*i+1],    dz = dirs[3*i+2];
    float inv_norm = rsqrtf(dx*dx + dy*dy + dz*dz);
    dx *= inv_norm; dy *= inv_norm; dz *= inv_norm;

    float vx = viewdirs[3*i+0], vy = viewdirs[3*i+1], vz = viewdirs[3*i+2];

    float sh[BASIS];
    sh[0] =  0.28209479177387814f;
    sh[1] = -0.4886025119029199f * vy;
    sh[2] =  0.4886025119029199f * vz;
    sh[3] = -0.4886025119029199f * vx;
    sh[4] =  1.0925484305920792f * vx * vy;
    sh[5] = -1.0925484305920792f * vy * vz;
    sh[6] =  0.31539156525252005f * (2.0f*vz*vz - vx*vx - vy*vy);
    sh[7] = -1.0925484305920792f * vx * vz;
    sh[8] =  0.5462742152960396f * (vx*vx - vy*vy);

    float idrx = 1.0f / (dx + 1e-9f);
    float idry = 1.0f / (dy + 1e-9f);
    float idrz = 1.0f / (dz + 1e-9f);

    float t1x = -ox * idrx, t2x = t1x + idrx;
    float t1y = -oy * idry, t2y = t1y + idry;
    float t1z = -oz * idrz, t2z = t1z + idrz;
    float tmin = fmaxf(fmaxf(fminf(t1x,t2x), fminf(t1y,t2y)), fminf(t1z,t2z));
    tmin = fmaxf(tmin, 0.0f);
    float tmax = fminf(fminf(fmaxf(t1x,t2x), fmaxf(t1y,t2y)), fmaxf(t1z,t2z));
    tmax = fminf(tmax, 1e9f);

    float irx = invradius[0], iry = invradius[1], irz = invradius[2];
    float dsx = dx / irx, dsy = dy / iry, dsz = dz / irz;
    float delta_scale = sqrtf(dsx*dsx + dsy*dsy + dsz*dsz);

    float t = tmin;
    float light = 1.0f;
    float out0 = 0.0f, out1 = 0.0f, out2 = 0.0f;
    const float cube_sz = 1.0f / (float)RR;

    #define GEOM(tt, dt_o, vp_o)                                               \
    {                                                                          \
        float px = fmaf((tt), dx, ox) * (float)RR;                             \
        float py = fmaf((tt), dy, oy) * (float)RR;                             \
        float pz = fmaf((tt), dz, oz) * (float)RR;                             \
        float fx = fminf(fmaxf(floorf(px), 0.0f), (float)(RR-1));              \
        float fy = fminf(fmaxf(floorf(py), 0.0f), (float)(RR-1));              \
        float fz = fminf(fmaxf(floorf(pz), 0.0f), (float)(RR-1));              \
        int flat = (int)fx * (RR*RR) + (int)fy * RR + (int)fz;                 \
        (vp_o) = g_grid + (size_t)flat * 4;                                    \
        float cx = px - fx, cy = py - fy, cz = pz - fz;                        \
        float u1x = -cx * idrx, u2x = u1x + idrx;                              \
        float u1y = -cy * idry, u2y = u1y + idry;                              \
        float u1z = -cz * idrz, u2z = u1z + idrz;                              \
        float s0 = fmaxf(fmaxf(fminf(u1x,u2x), fminf(u1y,u2y)), fminf(u1z,u2z)); \
        s0 = fmaxf(s0, 0.0f);                                                  \
        float s1 = fminf(fminf(fmaxf(u1x,u2x), fmaxf(u1y,u2y)), fmaxf(u1z,u2z)); \
        s1 = fminf(s1, 1e9f);                                                  \
        (dt_o) = (s1 - s0) * cube_sz + STEP_SIZE;                              \
    }

    #define SHADE(q0, q1, q2, q3, dtv)                                         \
    {                                                                          \
        __half hs[PAD_HALVES];                                                 \
        *reinterpret_cast<uint4*>(hs +  0) = (q0);                             \
        *reinterpret_cast<uint4*>(hs +  8) = (q1);                             \
        *reinterpret_cast<uint4*>(hs + 16) = (q2);                             \
        *reinterpret_cast<uint4*>(hs + 24) = (q3);                             \
        float sigma = fmaxf(__half2float(hs[27]), 0.0f);                       \
        float att = __expf(-(dtv) * sigma * delta_scale);                      \
        float weight = light * (1.0f - att);                                   \
        float c0 = 0.0f, c1 = 0.0f, c2 = 0.0f;                                 \
        _Pragma("unroll")                                                      \
        for (int j = 0; j < BASIS; ++j) {                                      \
            c0 = fmaf(sh[j], __half2float(hs[j]),            c0);              \
            c1 = fmaf(sh[j], __half2float(hs[BASIS + j]),    c1);              \
            c2 = fmaf(sh[j], __half2float(hs[2*BASIS + j]),  c2);              \
        }                                                                      \
        float r0 = __fdividef(1.0f, 1.0f + __expf(-c0));                       \
        float r1 = __fdividef(1.0f, 1.0f + __expf(-c1));                       \
        float r2 = __fdividef(1.0f, 1.0f + __expf(-c2));                       \
        out0 = fmaf(weight, r0, out0);                                         \
        out1 = fmaf(weight, r1, out1);                                         \
        out2 = fmaf(weight, r2, out2);                                         \
        light *= att;                                                          \
    }

    // Consume BUF (current step s), prefetch step s+2 into BUF, advance state.
    #define DO_STEP(B0, B1, B2, B3)                                            \
    {                                                                          \
        uint4 l0 = B0, l1 = B1, l2 = B2, l3 = B3;                              \
        float dtc = dt0;                                                       \
        float tn = t + dt0;                                                    \
        bool v2 = v1 && (s + 2 < NUM_STEPS) && (tn + dt1 < tmax);              \
        float dt2 = 0.0f;                                                      \
        if (v2) {                                                              \
            const uint4* vpn;                                                  \
            GEOM(tn + dt1, dt2, vpn);                                          \
            B0 = __ldg(vpn + 0); B1 = __ldg(vpn + 1);                          \
            B2 = __ldg(vpn + 2); B3 = __ldg(vpn + 3);                          \
        }                                                                      \
        SHADE(l0, l1, l2, l3, dtc);                                            \
        t = tn; dt0 = dt1; dt1 = dt2;                                          \
        bool cont = v1; v1 = v2;                                               \
        ++s;                                                                   \
        if (!cont) break;                                                      \
    }

    if (tmin < tmax) {
        // Prologue: load step 0 into A, step 1 (if any) into B.
        float dt0, dt1 = 0.0f;
        const uint4* vp;
        GEOM(t, dt0, vp);
        uint4 A0 = __ldg(vp + 0), A1 = __ldg(vp + 1),
              A2 = __ldg(vp + 2), A3 = __ldg(vp + 3);
        bool v1 = (t + dt0 < tmax);  // NUM_STEPS > 1 always
        uint4 B0, B1, B2, B3;
        if (v1) {
            const uint4* vpb;
            GEOM(t + dt0, dt1, vpb);
            B0 = __ldg(vpb + 0); B1 = __ldg(vpb + 1);
            B2 = __ldg(vpb + 2); B3 = __ldg(vpb + 3);
        }
        int s = 0;
        for (;;) {
            DO_STEP(A0, A1, A2, A3);   // even steps
            DO_STEP(B0, B1, B2, B3);   // odd steps
        }
    }
    #undef DO_STEP
    #undef SHADE
    #undef GEOM

    out[3*i+0] = out0 + light * BG;
    out[3*i+1] = out1 + light * BG;
    out[3*i+2] = out2 + light * BG;
}

extern "C" void kernel_launch(void* const* d_in, const int* in_sizes, int n_in,
                              void* d_out, int out_size)
{
    const float* tree      = (const float*)d_in[0];
    const float* origins   = (const float*)d_in[1];
    const float* dirs      = (const float*)d_in[2];
    const float* viewdirs  = (const float*)d_in[3];
    const float* invradius = (const float*)d_in[4];
    float* out = (float*)d_out;

    int nb = in_sizes[1] / 3;

    // Pass 1: repack grid to fp16/64B
    int n_u4 = NVOX * 4;
    convert_kernel<<<(n_u4 + 255) / 256, 256>>>(tree);

    // Pass 2: render
    int threads = 128;
    int blocks = (nb + threads - 1) / threads;
    volrend_kernel<<<blocks, threads>>>(origins, dirs, viewdirs, invradius, out, nb);
}